// round 2
// baseline (speedup 1.0000x reference)
#include <cuda_runtime.h>
#include <cuda_bf16.h>
#include <math.h>

// ---------------------------------------------------------------------------
// HGCN layer: h = mobius_matvec(W,x); h = mobius_add(h, expmap0(b));
//             h_t = logmap0(h); agg = scatter_add(h_t[src]*w -> dst) + h_t;
//             out = project(expmap0(prelu(logmap0(expmap0(agg)))))
// Shapes: N=100000, E=600000, D=128 (D hardcoded).
// ---------------------------------------------------------------------------

#define D 128
#define XPAD 132              // smem row stride (floats), keeps 16B alignment
#define TM 128                // rows per GEMM block
#define BT 256                // threads per GEMM block

// scratch: tangent-space features h_t (separate from agg buffer: scatter
// gathers h_t[src] while atomics hit agg[dst])
__device__ __align__(16) float g_ht[100352 * D];
__device__ __align__(16) float g_p[D];   // expmap0(b)
__device__ float g_p2;                   // |expmap0(b)|^2
__device__ int   g_stride;               // 1 = edge_index int32, 2 = int64

__device__ __forceinline__ float wsum(float v) {
#pragma unroll
    for (int o = 16; o; o >>= 1) v += __shfl_xor_sync(0xffffffffu, v, o);
    return v;
}

// ---------------------------------------------------------------------------
// K0a: detect edge_index dtype. View as int32 pairs; genuine int64 data has
// all-zero high words, int32 data has random indices there.
// ---------------------------------------------------------------------------
__global__ void k_detect(const int* __restrict__ ei32) {
    int t = threadIdx.x;                     // 256 threads
    int hi = ei32[2 * t + 1];
    unsigned any = __ballot_sync(0xffffffffu, hi != 0);
    __shared__ int s_any;
    if (t == 0) s_any = 0;
    __syncthreads();
    if ((t & 31) == 0 && any) atomicOr(&s_any, 1);
    __syncthreads();
    if (t == 0) g_stride = s_any ? 1 : 2;
}

// ---------------------------------------------------------------------------
// K0b: p = expmap0(b), p2 = |p|^2   (1 block, 128 threads)
// ---------------------------------------------------------------------------
__global__ void k_bias(const float* __restrict__ b) {
    __shared__ float red[4];
    int t = threadIdx.x;
    float v = b[t];
    float s = wsum(v * v);
    if ((t & 31) == 0) red[t >> 5] = s;
    __syncthreads();
    float n2 = red[0] + red[1] + red[2] + red[3];
    float n = fmaxf(sqrtf(n2), 1e-15f);
    float p = tanhf(n) * v / n;
    g_p[t] = p;
    __syncthreads();
    float s2 = wsum(p * p);
    if ((t & 31) == 0) red[t >> 5] = s2;
    __syncthreads();
    if (t == 0) g_p2 = red[0] + red[1] + red[2] + red[3];
}

// ---------------------------------------------------------------------------
// K1: fused mx = x @ W^T, mobius_matvec scaling, mobius_add(., p), logmap0.
//     Writes h_t to g_ht AND to out (agg initialized with the +h_t term).
// ---------------------------------------------------------------------------
__global__ void k_linear(const float* __restrict__ x, const float* __restrict__ W,
                         float* __restrict__ out, int N) {
    extern __shared__ float sm[];
    float* Xs = sm;                 // [D][XPAD]  Xs[k*XPAD + r]
    float* Wt = sm + D * XPAD;      // [D][XPAD]  Wt[k*XPAD + j]
    __shared__ float s_xn[TM];

    const int t = threadIdx.x;
    const int row0 = blockIdx.x * TM;

    for (int idx = t; idx < D * D; idx += BT) {
        int j = idx >> 7, k = idx & 127;
        Wt[k * XPAD + j] = W[idx];
    }
    for (int idx = t; idx < TM * D; idx += BT) {
        int r = idx >> 7, c = idx & 127;
        int g = row0 + r;
        Xs[c * XPAD + r] = (g < N) ? x[(size_t)g * D + c] : 0.f;
    }
    __syncthreads();

    // register-tiled fp32 GEMM: 16x16 threads, 8x8 micro-tile
    const int tx = t & 15, ty = t >> 4;
    const int r0 = ty * 8, j0 = tx * 8;
    float acc[8][8];
#pragma unroll
    for (int i = 0; i < 8; i++)
#pragma unroll
        for (int j = 0; j < 8; j++) acc[i][j] = 0.f;

#pragma unroll 4
    for (int k = 0; k < D; k++) {
        float4 a0 = *(const float4*)&Xs[k * XPAD + r0];
        float4 a1 = *(const float4*)&Xs[k * XPAD + r0 + 4];
        float4 b0 = *(const float4*)&Wt[k * XPAD + j0];
        float4 b1 = *(const float4*)&Wt[k * XPAD + j0 + 4];
        float av[8] = {a0.x, a0.y, a0.z, a0.w, a1.x, a1.y, a1.z, a1.w};
        float bv[8] = {b0.x, b0.y, b0.z, b0.w, b1.x, b1.y, b1.z, b1.w};
#pragma unroll
        for (int i = 0; i < 8; i++)
#pragma unroll
            for (int j = 0; j < 8; j++) acc[i][j] = fmaf(av[i], bv[j], acc[i][j]);
    }

    // per-row |x| (from Xs before it is overwritten)
    const int w = t >> 5, lane = t & 31;
#pragma unroll
    for (int rr = 0; rr < 16; rr++) {
        int r = w * 16 + rr;
        float s = 0.f;
#pragma unroll
        for (int kk = 0; kk < 4; kk++) {
            float v = Xs[(lane + kk * 32) * XPAD + r];
            s += v * v;
        }
        s = wsum(s);
        if (lane == 0) s_xn[r] = sqrtf(s);
    }
    __syncthreads();

    // dump MX[r][j] into the Xs region
#pragma unroll
    for (int i = 0; i < 8; i++) {
        *(float4*)&Xs[(r0 + i) * XPAD + j0] =
            make_float4(acc[i][0], acc[i][1], acc[i][2], acc[i][3]);
        *(float4*)&Xs[(r0 + i) * XPAD + j0 + 4] =
            make_float4(acc[i][4], acc[i][5], acc[i][6], acc[i][7]);
    }
    __syncthreads();

    // row-wise mobius math: warp w handles rows [w*16, w*16+16)
    float4 pr = *(const float4*)&g_p[lane * 4];
    const float y2 = g_p2;
    for (int rr = 0; rr < 16; rr++) {
        int r = w * 16 + rr;
        int g = row0 + r;
        if (g >= N) continue;   // uniform across warp
        float4 m = *(const float4*)&Xs[r * XPAD + lane * 4];

        float mxn2 = wsum(m.x * m.x + m.y * m.y + m.z * m.z + m.w * m.w);
        float mxn_raw = sqrtf(mxn2);
        float mxn = fmaxf(mxn_raw, 1e-15f);
        float xn = fmaxf(s_xn[r], 1e-15f);
        float artx = atanhf(fminf(xn, 1.f - 1e-7f));
        float sc = tanhf(mxn / xn * artx) / mxn;
        if (mxn_raw <= 1e-10f) sc = 0.f;   // mobius_matvec zero-mask

        float hx = m.x * sc, hy = m.y * sc, hz = m.z * sc, hw = m.w * sc;
        float x2 = sc * sc * mxn2;
        float xy = wsum(hx * pr.x + hy * pr.y + hz * pr.z + hw * pr.w);

        float c1 = 1.f + 2.f * xy + y2;
        float c2 = 1.f - x2;
        float den = fmaxf(1.f + 2.f * xy + x2 * y2, 1e-15f);
        float bx = (c1 * hx + c2 * pr.x) / den;
        float by = (c1 * hy + c2 * pr.y) / den;
        float bz = (c1 * hz + c2 * pr.z) / den;
        float bw = (c1 * hw + c2 * pr.w) / den;

        float n2b = wsum(bx * bx + by * by + bz * bz + bw * bw);
        float nb = fmaxf(sqrtf(n2b), 1e-15f);
        float sl = atanhf(fminf(nb, 1.f - 1e-7f)) / nb;
        float4 o = make_float4(bx * sl, by * sl, bz * sl, bw * sl);

        *(float4*)&g_ht[(size_t)g * D + lane * 4] = o;
        *(float4*)&out[(size_t)g * D + lane * 4] = o;   // agg init = h_t
    }
}

// ---------------------------------------------------------------------------
// K2: scatter-add. One warp per edge; each lane handles one float4.
// Index decode via g_stride: int32 data -> stride 1; int64 data -> stride 2
// (low word of each little-endian int64).
// ---------------------------------------------------------------------------
__global__ void k_scatter(const int* __restrict__ ei32,
                          const float* __restrict__ ew,
                          float* __restrict__ out, int E) {
    int gw = (int)((blockIdx.x * blockDim.x + threadIdx.x) >> 5);
    if (gw >= E) return;
    int lane = threadIdx.x & 31;
    int st = g_stride;
    int s = __ldg(ei32 + (size_t)gw * st);
    int d = __ldg(ei32 + ((size_t)E + gw) * st);
    float wgt = __ldg(ew + gw);
    const float4 v = *(const float4*)(g_ht + (size_t)s * D + lane * 4);
    float* p = out + (size_t)d * D + lane * 4;
    asm volatile("red.global.add.v4.f32 [%0], {%1,%2,%3,%4};"
                 :: "l"(p), "f"(v.x * wgt), "f"(v.y * wgt),
                    "f"(v.z * wgt), "f"(v.w * wgt)
                 : "memory");
}

// ---------------------------------------------------------------------------
// K3: finalize: logmap0(expmap0(agg)) -> prelu -> expmap0 -> project
// One warp per row, in-place on out.
// ---------------------------------------------------------------------------
__global__ void k_final(float* __restrict__ out, const float* __restrict__ a_ptr,
                        int N) {
    int gw = (int)((blockIdx.x * blockDim.x + threadIdx.x) >> 5);
    if (gw >= N) return;
    int lane = threadIdx.x & 31;
    float a = __ldg(a_ptr);
    float* p = out + (size_t)gw * D + lane * 4;
    float4 v = *(const float4*)p;

    // logmap0(expmap0(agg)) = atanh(min(tanh(n),1-1e-7))/n * agg
    float n1 = fmaxf(sqrtf(wsum(v.x * v.x + v.y * v.y + v.z * v.z + v.w * v.w)),
                     1e-15f);
    float s = atanhf(fminf(tanhf(n1), 1.f - 1e-7f)) / n1;
    float tx = v.x * s, ty = v.y * s, tz = v.z * s, tw = v.w * s;
    tx = tx >= 0.f ? tx : a * tx;
    ty = ty >= 0.f ? ty : a * ty;
    tz = tz >= 0.f ? tz : a * tz;
    tw = tw >= 0.f ? tw : a * tw;
    float n3 = fmaxf(sqrtf(wsum(tx * tx + ty * ty + tz * tz + tw * tw)), 1e-15f);
    float th = tanhf(n3);
    float s2 = th / n3;
    float ox = tx * s2, oy = ty * s2, oz = tz * s2, ow = tw * s2;
    float n4 = fmaxf(th, 1e-15f);
    const float maxn = 1.f - 4e-3f;
    if (n4 > maxn) {
        float f = maxn / n4;
        ox *= f; oy *= f; oz *= f; ow *= f;
    }
    *(float4*)p = make_float4(ox, oy, oz, ow);
}

// ---------------------------------------------------------------------------
extern "C" void kernel_launch(void* const* d_in, const int* in_sizes, int n_in,
                              void* d_out, int out_size) {
    const float* x    = (const float*)d_in[0];
    const int*   ei32 = (const int*)d_in[1];     // int32 view; dtype detected
    const float* ew   = (const float*)d_in[2];
    const float* W    = (const float*)d_in[3];
    const float* b    = (const float*)d_in[4];
    const float* a    = (const float*)d_in[5];
    float* out = (float*)d_out;

    int N = in_sizes[0] / D;
    int E = in_sizes[2];

    k_detect<<<1, 256>>>(ei32);
    k_bias<<<1, 128>>>(b);

    size_t smem = (size_t)2 * D * XPAD * sizeof(float);   // 135168 B
    cudaFuncSetAttribute(k_linear, cudaFuncAttributeMaxDynamicSharedMemorySize,
                         (int)smem);
    k_linear<<<(N + TM - 1) / TM, BT, smem>>>(x, W, out, N);

    k_scatter<<<(E + 7) / 8, 256>>>(ei32, ew, out, E);

    k_final<<<(N + 7) / 8, 256>>>(out, a, N);
}

// round 4
// speedup vs baseline: 1.8148x; 1.8148x over previous
#include <cuda_runtime.h>
#include <cuda_bf16.h>
#include <math.h>
#include <stdint.h>

// ---------------------------------------------------------------------------
// HGCN layer. GEMM via mma.sync bf16 (3-term hi/lo split, fp32 accum) +
// fused mobius epilogue; edge scatter via red.global.add.v4.f32; fused final.
// N=100000, E=600000, D=128.
// NOTE: tcgen05 is NOT available (harness PTX targets sm_103, no 'a').
// ---------------------------------------------------------------------------

#define D 128
#define THREADS 256
#define RSTRIDE 272            // bytes per padded bf16 row (128 bf16 + 8 pad)

__device__ __align__(16) float g_ht[100352 * D];
__device__ __align__(16) float g_p[D];   // expmap0(b)
__device__ float g_p2;                   // |expmap0(b)|^2
__device__ int   g_stride;               // 1 = edge_index int32, 2 = int64

__device__ __forceinline__ float wsum(float v) {
#pragma unroll
    for (int o = 16; o; o >>= 1) v += __shfl_xor_sync(0xffffffffu, v, o);
    return v;
}

__device__ __forceinline__ float qsum(float v) {   // reduce within 4-lane quad
    v += __shfl_xor_sync(0xffffffffu, v, 1);
    v += __shfl_xor_sync(0xffffffffu, v, 2);
    return v;
}

__device__ __forceinline__ void mma_bf16(float* c, const uint32_t* a,
                                         const uint32_t* b) {
    asm volatile(
        "mma.sync.aligned.m16n8k16.row.col.f32.bf16.bf16.f32 "
        "{%0,%1,%2,%3}, {%4,%5,%6,%7}, {%8,%9}, {%0,%1,%2,%3};"
        : "+f"(c[0]), "+f"(c[1]), "+f"(c[2]), "+f"(c[3])
        : "r"(a[0]), "r"(a[1]), "r"(a[2]), "r"(a[3]), "r"(b[0]), "r"(b[1]));
}

// dynamic smem layout (bytes)
#define S_XH 0
#define S_XL (S_XH + 128 * RSTRIDE)     // 34816
#define S_WH (S_XL + 128 * RSTRIDE)     // 69632
#define S_WL (S_WH + 128 * RSTRIDE)     // 104448
#define S_TOTAL (S_WL + 128 * RSTRIDE)  // 139264
#define S_OUT 0                         // f32 staging overlay (post-MMA)

// ---------------------------------------------------------------------------
// K0a: detect edge_index dtype (int32 vs int64 low words)
// ---------------------------------------------------------------------------
__global__ void k_detect(const int* __restrict__ ei32) {
    int t = threadIdx.x;
    int hi = ei32[2 * t + 1];
    unsigned any = __ballot_sync(0xffffffffu, hi != 0);
    __shared__ int s_any;
    if (t == 0) s_any = 0;
    __syncthreads();
    if ((t & 31) == 0 && any) atomicOr(&s_any, 1);
    __syncthreads();
    if (t == 0) g_stride = s_any ? 1 : 2;
}

// ---------------------------------------------------------------------------
// K0b: p = expmap0(b), p2 = |p|^2
// ---------------------------------------------------------------------------
__global__ void k_bias(const float* __restrict__ b) {
    __shared__ float red[4];
    int t = threadIdx.x;
    float v = b[t];
    float s = wsum(v * v);
    if ((t & 31) == 0) red[t >> 5] = s;
    __syncthreads();
    float n2 = red[0] + red[1] + red[2] + red[3];
    float n = fmaxf(sqrtf(n2), 1e-15f);
    float p = tanhf(n) * v / n;
    g_p[t] = p;
    __syncthreads();
    float s2 = wsum(p * p);
    if ((t & 31) == 0) red[t >> 5] = s2;
    __syncthreads();
    if (t == 0) g_p2 = red[0] + red[1] + red[2] + red[3];
}

// ---------------------------------------------------------------------------
// load helper: read rows (float4/lane), optionally record |row|^2, write
// bf16 hi/lo into padded smem [row][col] (RSTRIDE bytes per row).
// ---------------------------------------------------------------------------
__device__ __forceinline__ void load_split(const float* __restrict__ src,
                                           char* sm, int bh, int bl,
                                           int t, bool do_norm, float* xn2,
                                           int row0, int N) {
    int w = t >> 5, lane = t & 31;
#pragma unroll 4
    for (int i = 0; i < 16; i++) {
        int r = i * 8 + w;
        float4 v;
        if (do_norm) {
            int g = row0 + r;
            v = (g < N) ? *(const float4*)(src + (size_t)g * D + lane * 4)
                        : make_float4(0.f, 0.f, 0.f, 0.f);
            float s = wsum(v.x * v.x + v.y * v.y + v.z * v.z + v.w * v.w);
            if (lane == 0) xn2[r] = s;
        } else {
            v = *(const float4*)(src + (size_t)r * D + lane * 4);
        }
        __nv_bfloat16 hx = __float2bfloat16_rn(v.x);
        __nv_bfloat16 hy = __float2bfloat16_rn(v.y);
        __nv_bfloat16 hz = __float2bfloat16_rn(v.z);
        __nv_bfloat16 hw = __float2bfloat16_rn(v.w);
        __nv_bfloat16 lx = __float2bfloat16_rn(v.x - __bfloat162float(hx));
        __nv_bfloat16 ly = __float2bfloat16_rn(v.y - __bfloat162float(hy));
        __nv_bfloat16 lz = __float2bfloat16_rn(v.z - __bfloat162float(hz));
        __nv_bfloat16 lw = __float2bfloat16_rn(v.w - __bfloat162float(hw));
        __nv_bfloat162 h01; h01.x = hx; h01.y = hy;   // low 16 bits = lower k
        __nv_bfloat162 h23; h23.x = hz; h23.y = hw;
        __nv_bfloat162 l01; l01.x = lx; l01.y = ly;
        __nv_bfloat162 l23; l23.x = lz; l23.y = lw;
        uint2 hv = make_uint2(*(uint32_t*)&h01, *(uint32_t*)&h23);
        uint2 lv = make_uint2(*(uint32_t*)&l01, *(uint32_t*)&l23);
        int off = r * RSTRIDE + 8 * lane;     // bf16 col 4*lane
        *(uint2*)(sm + bh + off) = hv;
        *(uint2*)(sm + bl + off) = lv;
    }
}

// mobius scalar pipeline: given |mx|^2, mx.p, |x|^2 -> (alpha, beta)
__device__ __forceinline__ float2 mobius_ab(float mxn2, float mp, float xnn2,
                                            float y2) {
    float mxn_raw = sqrtf(mxn2);
    float mxn = fmaxf(mxn_raw, 1e-15f);
    float xn = fmaxf(sqrtf(xnn2), 1e-15f);
    float artx = atanhf(fminf(xn, 1.f - 1e-7f));
    float sc = tanhf(mxn / xn * artx) / mxn;
    if (mxn_raw <= 1e-10f) sc = 0.f;
    float x2 = sc * sc * mxn2;
    float xy = sc * mp;
    float c1 = 1.f + 2.f * xy + y2;
    float c2v = 1.f - x2;
    float den = fmaxf(1.f + 2.f * xy + x2 * y2, 1e-15f);
    float nb2 = (c1 * c1 * x2 + 2.f * c1 * c2v * xy + c2v * c2v * y2) /
                (den * den);
    float nb = fmaxf(sqrtf(nb2), 1e-15f);
    float sl = atanhf(fminf(nb, 1.f - 1e-7f)) / nb;
    return make_float2(sl * c1 * sc / den, sl * c2v / den);
}

// ---------------------------------------------------------------------------
// K1: bf16-split mma.sync GEMM + mobius epilogue. 128 rows/CTA, 256 threads.
// Warp w owns rows 16w..16w+15; fragment addressing is direct from padded
// smem (row stride 272 B keeps the (g,tg) pattern bank-conflict-free).
// ---------------------------------------------------------------------------
__global__ void __launch_bounds__(THREADS, 1)
k_linear(const float* __restrict__ x, const float* __restrict__ W,
         float* __restrict__ out, int N) {
    extern __shared__ char sm[];
    __shared__ float xn2[128];
    __shared__ float p_s[128];

    const int t = threadIdx.x;
    const int w = t >> 5, lane = t & 31;
    const int g4 = lane >> 2, tg = lane & 3;
    const int row0 = blockIdx.x * 128;

    if (t < 128) p_s[t] = g_p[t];

    load_split(x, sm, S_XH, S_XL, t, true, xn2, row0, N);
    load_split(W, sm, S_WH, S_WL, t, false, xn2, 0, N);
    __syncthreads();

    // ---- MMA mainloop ----
    float acc[16][4];
#pragma unroll
    for (int nt = 0; nt < 16; nt++)
#pragma unroll
        for (int j = 0; j < 4; j++) acc[nt][j] = 0.f;

    const char* Xh = sm + S_XH;
    const char* Xl = sm + S_XL;
    const char* Wh = sm + S_WH;
    const char* Wl = sm + S_WL;
    const int ra = (16 * w + g4) * RSTRIDE;      // A row byte base
    const int ka0 = 4 * tg;                      // k-pair byte offset

#pragma unroll
    for (int ks = 0; ks < 8; ks++) {
        const int kb = 32 * ks + ka0;
        uint32_t ah[4], al[4];
        ah[0] = *(const uint32_t*)(Xh + ra + kb);
        ah[1] = *(const uint32_t*)(Xh + ra + 8 * RSTRIDE + kb);
        ah[2] = *(const uint32_t*)(Xh + ra + kb + 16);
        ah[3] = *(const uint32_t*)(Xh + ra + 8 * RSTRIDE + kb + 16);
        al[0] = *(const uint32_t*)(Xl + ra + kb);
        al[1] = *(const uint32_t*)(Xl + ra + 8 * RSTRIDE + kb);
        al[2] = *(const uint32_t*)(Xl + ra + kb + 16);
        al[3] = *(const uint32_t*)(Xl + ra + 8 * RSTRIDE + kb + 16);
#pragma unroll
        for (int nt = 0; nt < 16; nt++) {
            const int rb = (8 * nt + g4) * RSTRIDE;
            uint32_t bh[2], bl[2];
            bh[0] = *(const uint32_t*)(Wh + rb + kb);
            bh[1] = *(const uint32_t*)(Wh + rb + kb + 16);
            bl[0] = *(const uint32_t*)(Wl + rb + kb);
            bl[1] = *(const uint32_t*)(Wl + rb + kb + 16);
            mma_bf16(acc[nt], ah, bh);
            mma_bf16(acc[nt], ah, bl);
            mma_bf16(acc[nt], al, bh);
        }
    }
    __syncthreads();    // X/W no longer needed; smem reused for staging

    // ---- epilogue ----
    // thread holds rows r0=16w+g4 (c0,c1) and r1=r0+8 (c2,c3),
    // cols {8nt+2tg, 8nt+2tg+1}.
    float n2a = 0.f, mpa = 0.f, n2b = 0.f, mpb = 0.f;
#pragma unroll
    for (int nt = 0; nt < 16; nt++) {
        float p0 = p_s[8 * nt + 2 * tg], p1 = p_s[8 * nt + 2 * tg + 1];
        n2a = fmaf(acc[nt][0], acc[nt][0], fmaf(acc[nt][1], acc[nt][1], n2a));
        mpa = fmaf(acc[nt][0], p0, fmaf(acc[nt][1], p1, mpa));
        n2b = fmaf(acc[nt][2], acc[nt][2], fmaf(acc[nt][3], acc[nt][3], n2b));
        mpb = fmaf(acc[nt][2], p0, fmaf(acc[nt][3], p1, mpb));
    }
    n2a = qsum(n2a); mpa = qsum(mpa);
    n2b = qsum(n2b); mpb = qsum(mpb);

    const int r0 = 16 * w + g4, r1 = r0 + 8;
    const float y2 = g_p2;
    float2 ab0 = mobius_ab(n2a, mpa, xn2[r0], y2);
    float2 ab1 = mobius_ab(n2b, mpb, xn2[r1], y2);

    float* stg = (float*)(sm + S_OUT);           // [128][132] f32
#pragma unroll
    for (int nt = 0; nt < 16; nt++) {
        int c = 8 * nt + 2 * tg;
        float p0 = p_s[c], p1 = p_s[c + 1];
        *(float2*)&stg[r0 * 132 + c] = make_float2(
            fmaf(ab0.x, acc[nt][0], ab0.y * p0),
            fmaf(ab0.x, acc[nt][1], ab0.y * p1));
        *(float2*)&stg[r1 * 132 + c] = make_float2(
            fmaf(ab1.x, acc[nt][2], ab1.y * p0),
            fmaf(ab1.x, acc[nt][3], ab1.y * p1));
    }
    __syncthreads();

    // coalesced flush: warp covers one full row per iter
#pragma unroll 2
    for (int idx = t; idx < 128 * 32; idx += THREADS) {
        int r2 = idx >> 5, c4 = idx & 31;
        int g = row0 + r2;
        if (g < N) {
            float4 v = *(const float4*)&stg[r2 * 132 + c4 * 4];
            *(float4*)&g_ht[(size_t)g * D + c4 * 4] = v;
            *(float4*)&out[(size_t)g * D + c4 * 4] = v;   // agg init = h_t
        }
    }
}

// ---------------------------------------------------------------------------
// K2: scatter-add. One warp per edge; lane handles one float4.
// ---------------------------------------------------------------------------
__global__ void k_scatter(const int* __restrict__ ei32,
                          const float* __restrict__ ew,
                          float* __restrict__ out, int E) {
    int gw = (int)((blockIdx.x * blockDim.x + threadIdx.x) >> 5);
    if (gw >= E) return;
    int lane = threadIdx.x & 31;
    int st = g_stride;
    int s = __ldg(ei32 + (size_t)gw * st);
    int d = __ldg(ei32 + ((size_t)E + gw) * st);
    float wgt = __ldg(ew + gw);
    const float4 v = *(const float4*)(g_ht + (size_t)s * D + lane * 4);
    float* p = out + (size_t)d * D + lane * 4;
    asm volatile("red.global.add.v4.f32 [%0], {%1,%2,%3,%4};"
                 :: "l"(p), "f"(v.x * wgt), "f"(v.y * wgt),
                    "f"(v.z * wgt), "f"(v.w * wgt)
                 : "memory");
}

// ---------------------------------------------------------------------------
// K3: finalize: logmap0(expmap0(agg)) -> prelu -> expmap0 -> project
// ---------------------------------------------------------------------------
__global__ void k_final(float* __restrict__ out, const float* __restrict__ a_ptr,
                        int N) {
    int gw = (int)((blockIdx.x * blockDim.x + threadIdx.x) >> 5);
    if (gw >= N) return;
    int lane = threadIdx.x & 31;
    float a = __ldg(a_ptr);
    float* p = out + (size_t)gw * D + lane * 4;
    float4 v = *(const float4*)p;

    float n1 = fmaxf(sqrtf(wsum(v.x * v.x + v.y * v.y + v.z * v.z + v.w * v.w)),
                     1e-15f);
    float s = atanhf(fminf(tanhf(n1), 1.f - 1e-7f)) / n1;
    float tx = v.x * s, ty = v.y * s, tz = v.z * s, tw = v.w * s;
    tx = tx >= 0.f ? tx : a * tx;
    ty = ty >= 0.f ? ty : a * ty;
    tz = tz >= 0.f ? tz : a * tz;
    tw = tw >= 0.f ? tw : a * tw;
    float n3 = fmaxf(sqrtf(wsum(tx * tx + ty * ty + tz * tz + tw * tw)), 1e-15f);
    float th = tanhf(n3);
    float s2 = th / n3;
    float ox = tx * s2, oy = ty * s2, oz = tz * s2, ow = tw * s2;
    float n4 = fmaxf(th, 1e-15f);
    const float maxn = 1.f - 4e-3f;
    if (n4 > maxn) {
        float f = maxn / n4;
        ox *= f; oy *= f; oz *= f; ow *= f;
    }
    *(float4*)p = make_float4(ox, oy, oz, ow);
}

// ---------------------------------------------------------------------------
extern "C" void kernel_launch(void* const* d_in, const int* in_sizes, int n_in,
                              void* d_out, int out_size) {
    const float* x    = (const float*)d_in[0];
    const int*   ei32 = (const int*)d_in[1];
    const float* ew   = (const float*)d_in[2];
    const float* W    = (const float*)d_in[3];
    const float* b    = (const float*)d_in[4];
    const float* a    = (const float*)d_in[5];
    float* out = (float*)d_out;

    int N = in_sizes[0] / D;
    int E = in_sizes[2];

    k_detect<<<1, 256>>>(ei32);
    k_bias<<<1, 128>>>(b);

    cudaFuncSetAttribute(k_linear, cudaFuncAttributeMaxDynamicSharedMemorySize,
                         S_TOTAL);
    k_linear<<<(N + 127) / 128, THREADS, S_TOTAL>>>(x, W, out, N);

    k_scatter<<<(E + 7) / 8, 256>>>(ei32, ew, out, E);

    k_final<<<(N + 7) / 8, 256>>>(out, a, N);
}